// round 3
// baseline (speedup 1.0000x reference)
#include <cuda_runtime.h>
#include <math.h>

#define Bsz 32
#define Ssz 512
#define Esz 256
#define HDz 256
#define Hsz 512
#define Lsz 32
#define NG  1024   // 4*HD gate rows per direction

// ------------------- scratch -------------------
__device__ float g_x0[Bsz * Ssz * Esz];                 // embed out
__device__ float g_gx[2 * Bsz * Ssz * NG];              // gate preacts, both dirs
__device__ float g_h0[Bsz * Ssz * Hsz];                 // layer0 out
__device__ float g_h1[Bsz * Ssz * Hsz];                 // layer1 out
__device__ float g_ring[2 * 2 * Bsz * HDz];             // [dir][buf][batch][unit]
__device__ unsigned long long g_bar_cnt = 0ull;
__device__ unsigned long long g_bar_gen = 0ull;

// ------------------- packed f32x2 helpers -------------------
__device__ __forceinline__ void dfma2(unsigned long long& d, unsigned long long a,
                                      unsigned long long b) {
    asm("fma.rn.f32x2 %0, %1, %2, %0;" : "+l"(d) : "l"(a), "l"(b));
}
__device__ __forceinline__ float2 up2(unsigned long long v) {
    float2 f;
    asm("mov.b64 {%0, %1}, %2;" : "=f"(f.x), "=f"(f.y) : "l"(v));
    return f;
}

// ------------------- embed -------------------
__global__ void k_embed(const int* __restrict__ x, const float* __restrict__ emb,
                        float* __restrict__ out) {
    int row = blockIdx.x;
    int t = threadIdx.x;               // 64 threads
    int tok = x[row];
    const float4* s = (const float4*)(emb + (size_t)tok * Esz);
    ((float4*)(out + (size_t)row * Esz))[t] = s[t];
}

// ------------------- GEMM: C[M,N] = A[M,K] @ W[N,K]^T + b1 + b2 -------------------
// BM=BN=128, BK=8, 256 threads, 8x8 per thread, FMA2 packed along N
__global__ __launch_bounds__(256) void k_gemm(const float* __restrict__ A,
                                              const float* __restrict__ W,
                                              const float* __restrict__ b1,
                                              const float* __restrict__ b2,
                                              float* __restrict__ C,
                                              int K, int N) {
    __shared__ __align__(16) float As2[8 * 256];   // [k][m] duplicated float2
    __shared__ __align__(16) float Bs[8][132];
    int m0 = blockIdx.y * 128, n0 = blockIdx.x * 128;
    int tid = threadIdx.x;
    int tx = tid & 15, ty = tid >> 4;
    int lr = tid >> 1;
    int lk = (tid & 1) * 4;
    const float* Ap = A + (size_t)(m0 + lr) * K + lk;
    const float* Wp = W + (size_t)(n0 + lr) * K + lk;

    unsigned long long acc[8][4];
#pragma unroll
    for (int i = 0; i < 8; i++)
#pragma unroll
        for (int j = 0; j < 4; j++) acc[i][j] = 0ull;

    float4 av = *(const float4*)(Ap);
    float4 bv = *(const float4*)(Wp);
    float2* Ad = (float2*)As2;

    for (int k0 = 0; k0 < K; k0 += 8) {
        __syncthreads();
        Ad[(lk + 0) * 128 + lr] = make_float2(av.x, av.x);
        Ad[(lk + 1) * 128 + lr] = make_float2(av.y, av.y);
        Ad[(lk + 2) * 128 + lr] = make_float2(av.z, av.z);
        Ad[(lk + 3) * 128 + lr] = make_float2(av.w, av.w);
        Bs[lk + 0][lr] = bv.x; Bs[lk + 1][lr] = bv.y;
        Bs[lk + 2][lr] = bv.z; Bs[lk + 3][lr] = bv.w;
        __syncthreads();
        float4 av_n = av, bv_n = bv;
        if (k0 + 8 < K) {
            av_n = *(const float4*)(Ap + k0 + 8);
            bv_n = *(const float4*)(Wp + k0 + 8);
        }
#pragma unroll
        for (int kk = 0; kk < 8; kk++) {
            const ulonglong2* ap = (const ulonglong2*)(As2 + kk * 256);
            ulonglong2 aA = ap[ty * 2];
            ulonglong2 aB = ap[ty * 2 + 1];
            ulonglong2 aC = ap[32 + ty * 2];
            ulonglong2 aD = ap[32 + ty * 2 + 1];
            ulonglong2 bb0 = *(const ulonglong2*)&Bs[kk][4 * tx];
            ulonglong2 bb1 = *(const ulonglong2*)&Bs[kk][64 + 4 * tx];
            unsigned long long a_[8] = {aA.x, aA.y, aB.x, aB.y, aC.x, aC.y, aD.x, aD.y};
            unsigned long long b_[4] = {bb0.x, bb0.y, bb1.x, bb1.y};
#pragma unroll
            for (int i = 0; i < 8; i++)
#pragma unroll
                for (int j = 0; j < 4; j++) dfma2(acc[i][j], a_[i], b_[j]);
        }
        av = av_n; bv = bv_n;
    }

#pragma unroll
    for (int i = 0; i < 8; i++) {
        int r = m0 + ((i < 4) ? ty * 4 + i : 64 + ty * 4 + i - 4);
#pragma unroll
        for (int j = 0; j < 4; j++) {
            int nb = n0 + ((j < 2) ? 4 * tx + 2 * j : 64 + 4 * tx + 2 * (j - 2));
            float2 f = up2(acc[i][j]);
            C[(size_t)r * N + nb]     = f.x + b1[nb] + b2[nb];
            C[(size_t)r * N + nb + 1] = f.y + b1[nb + 1] + b2[nb + 1];
        }
    }
}

// ------------------- grid barrier (128 co-resident CTAs, acq/rel) -------------------
__device__ __forceinline__ void grid_bar() {
    __syncthreads();
    if (threadIdx.x == 0) {
        unsigned long long one = 1ull, tk;
        asm volatile("atom.acq_rel.gpu.add.u64 %0, [%1], %2;"
                     : "=l"(tk) : "l"(&g_bar_cnt), "l"(one) : "memory");
        unsigned long long target = tk / 128ull + 1ull;
        if ((tk & 127ull) == 127ull) {
            asm volatile("st.release.gpu.u64 [%0], %1;"
                         :: "l"(&g_bar_gen), "l"(target) : "memory");
        } else {
            unsigned long long g;
            do {
                asm volatile("ld.acquire.gpu.u64 %0, [%1];"
                             : "=l"(g) : "l"(&g_bar_gen) : "memory");
            } while (g < target);
        }
    }
    __syncthreads();
}

__device__ __forceinline__ float sigm(float x) { return 1.f / (1.f + expf(-x)); }

// ------------------- BiLSTM recurrence (one layer, both dirs) -------------------
// grid 128 CTAs x 128 threads. CTA: dir = bid>>6, chunk = bid&63 -> units [4c,4c+4)
// thread: cg = tid>>4 (cols 2cg,2cg+1 of col=ul*4+gate), bg = tid&15 (batches 2bg,2bg+1)
#define WPITCH 260
#define HPITCH 268
__global__ __launch_bounds__(128) void k_recur(const float* __restrict__ gx,
                                               const float* __restrict__ w_hh,
                                               const int* __restrict__ xlen,
                                               float* __restrict__ hout) {
    extern __shared__ float sm[];
    float* w_s = sm;                     // [16][WPITCH]
    float* h_s = sm + 16 * WPITCH;       // [32][HPITCH], row rb = (b>>1)+(b&1)*16
    int dir = blockIdx.x >> 6;
    int chunk = blockIdx.x & 63;
    int u0 = chunk * 4;
    int tid = threadIdx.x;
    int cg = tid >> 4, bg = tid & 15;
    int c0 = 2 * cg, c1 = 2 * cg + 1;
    int parity = cg & 1;
    int ul = cg >> 1;
    int myb = 2 * bg + parity;
    int ug = u0 + ul;

    const float* wd = w_hh + (size_t)dir * NG * HDz;
    const float* gxd = gx + (size_t)dir * Bsz * Ssz * NG;
    float* ring = g_ring + dir * 2 * (Bsz * HDz);

    for (int idx = tid; idx < 4096; idx += 128) {
        int col = idx >> 8;
        int k = idx & 255;
        int gate = col & 3, u_l = col >> 2;
        w_s[col * WPITCH + k] = wd[(size_t)(gate * 256 + u0 + u_l) * HDz + k];
    }

    ring[(size_t)myb * HDz + ug] = 0.f;   // zero buf0 cell

    int len0 = xlen[2 * bg], len1 = xlen[2 * bg + 1];
    int mylen = parity ? len1 : len0;

    int grow0 = (c0 & 3) * 256 + u0 + (c0 >> 2);
    int grow1 = (c1 & 3) * 256 + u0 + (c1 >> 2);

    float c_st = 0.f, h_st = 0.f;
    grid_bar();

    for (int t = 0; t < 512; t++) {
        // stage h ring -> smem (transposed row remap)
        const float4* rc = (const float4*)(ring + (t & 1) * (Bsz * HDz));
#pragma unroll
        for (int j = 0; j < 16; j++) {
            int idx = tid + j * 128;
            float4 v = __ldcv(rc + idx);
            int b = idx >> 6;
            int kq = idx & 63;
            int rb = (b >> 1) + (b & 1) * 16;
            *(float4*)&h_s[rb * HPITCH + 4 * kq] = v;
        }

        int s0 = t, s1 = t;
        if (dir) {
            s0 = (t < len0) ? (len0 - 1 - t) : t;
            s1 = (t < len1) ? (len1 - 1 - t) : t;
        }
        float g00 = __ldg(&gxd[((size_t)(2 * bg) * Ssz + s0) * NG + grow0]);
        float g01 = __ldg(&gxd[((size_t)(2 * bg + 1) * Ssz + s1) * NG + grow0]);
        float g10 = __ldg(&gxd[((size_t)(2 * bg) * Ssz + s0) * NG + grow1]);
        float g11 = __ldg(&gxd[((size_t)(2 * bg + 1) * Ssz + s1) * NG + grow1]);
        __syncthreads();

        unsigned long long acc00 = 0, acc01 = 0, acc10 = 0, acc11 = 0;
        const ulonglong2* w0p = (const ulonglong2*)&w_s[c0 * WPITCH];
        const ulonglong2* w1p = (const ulonglong2*)&w_s[c1 * WPITCH];
        const ulonglong2* h0p = (const ulonglong2*)&h_s[bg * HPITCH];
        const ulonglong2* h1p = (const ulonglong2*)&h_s[(16 + bg) * HPITCH];
#pragma unroll 4
        for (int kq = 0; kq < 64; kq++) {
            ulonglong2 w0 = w0p[kq];
            ulonglong2 w1 = w1p[kq];
            ulonglong2 ha = h0p[kq];
            ulonglong2 hb = h1p[kq];
            dfma2(acc00, w0.x, ha.x); dfma2(acc00, w0.y, ha.y);
            dfma2(acc01, w0.x, hb.x); dfma2(acc01, w0.y, hb.y);
            dfma2(acc10, w1.x, ha.x); dfma2(acc10, w1.y, ha.y);
            dfma2(acc11, w1.x, hb.x); dfma2(acc11, w1.y, hb.y);
        }
        float2 f00 = up2(acc00), f01 = up2(acc01), f10 = up2(acc10), f11 = up2(acc11);
        float a00 = f00.x + f00.y + g00;
        float a01 = f01.x + f01.y + g01;
        float a10 = f10.x + f10.y + g10;
        float a11 = f11.x + f11.y + g11;

        // even cg holds (i,f) of unit ul; odd cg holds (g,o). exchange across xor-16.
        float send0 = parity ? a00 : a01;   // odd: g_b0  | even: i_b1
        float send1 = parity ? a10 : a11;   // odd: o_b0  | even: f_b1
        float r0 = __shfl_xor_sync(0xffffffffu, send0, 16);
        float r1 = __shfl_xor_sync(0xffffffffu, send1, 16);
        float gi, gf, gg, go;
        if (!parity) { gi = a00; gf = a10; gg = r0;  go = r1;  }   // cell (ul, b0)
        else         { gi = r0;  gf = r1;  gg = a01; go = a11; }   // cell (ul, b1)

        float iv = sigm(gi), fv = sigm(gf), ov = sigm(go), gv = tanhf(gg);
        float cn = fv * c_st + iv * gv;
        float hn = ov * tanhf(cn);
        bool m = t < mylen;
        c_st = m ? cn : c_st;
        h_st = m ? hn : h_st;
        float outv = m ? hn : 0.f;

        ring[((t + 1) & 1) * (Bsz * HDz) + (size_t)myb * HDz + ug] = h_st;
        int pos, col;
        if (!dir) { pos = t; col = ug; }
        else      { pos = m ? (mylen - 1 - t) : t; col = 256 + ug; }
        hout[((size_t)myb * Ssz + pos) * Hsz + col] = outv;

        grid_bar();
    }
}

// ------------------- emissions: out[M,32] = h[M,512] @ dw[32,512]^T + db -------------------
__global__ __launch_bounds__(256) void k_emis(const float* __restrict__ h,
                                              const float* __restrict__ dw,
                                              const float* __restrict__ db,
                                              float* __restrict__ out) {
    __shared__ float wT[128 * 33];
    __shared__ float hs[32 * 128];
    int tid = threadIdx.x;
    int w = tid >> 5, j = tid & 31;
    int row0 = blockIdx.x * 32;
    float acc[4] = {0.f, 0.f, 0.f, 0.f};
    for (int kc = 0; kc < 4; kc++) {
        __syncthreads();
        for (int idx = tid; idx < 4096; idx += 256) {
            int jj = idx >> 7, k = idx & 127;
            wT[k * 33 + jj] = dw[(size_t)jj * 512 + kc * 128 + k];
        }
        for (int idx = tid; idx < 4096; idx += 256) {
            int r = idx >> 7, k = idx & 127;
            hs[r * 128 + k] = h[(size_t)(row0 + r) * 512 + kc * 128 + k];
        }
        __syncthreads();
#pragma unroll 4
        for (int k = 0; k < 128; k++) {
            float wv = wT[k * 33 + j];
#pragma unroll
            for (int i = 0; i < 4; i++) acc[i] += hs[(w * 4 + i) * 128 + k] * wv;
        }
    }
    float bias = db[j];
#pragma unroll
    for (int i = 0; i < 4; i++)
        out[(size_t)(row0 + w * 4 + i) * 32 + j] = acc[i] + bias;
}

// ------------------- Viterbi: 32 blocks x 32 threads -------------------
__global__ void k_viterbi(const float* __restrict__ em, const int* __restrict__ xlen,
                          const float* __restrict__ trans, const float* __restrict__ st,
                          const float* __restrict__ et,
                          float* __restrict__ tags_out, float* __restrict__ scores_out) {
    __shared__ unsigned char bp[512][32];
    int b = blockIdx.x, j = threadIdx.x;
    int len = xlen[b];
    float tc[32];
#pragma unroll
    for (int i = 0; i < 32; i++) tc[i] = trans[i * 32 + j];
    const float* e = em + (size_t)b * Ssz * Lsz;
    float alpha = st[j] + e[j];
    for (int t = 1; t < 512; t++) {
        if (t < len) {
            float best = -1e30f; int arg = 0;
#pragma unroll
            for (int i = 0; i < 32; i++) {
                float ai = __shfl_sync(0xffffffffu, alpha, i);
                float cand = ai + tc[i];
                if (cand > best) { best = cand; arg = i; }
            }
            alpha = best + e[(size_t)t * 32 + j];
            bp[t][j] = (unsigned char)arg;
        } else {
            bp[t][j] = (unsigned char)j;
        }
    }
    __syncwarp();
    float fin = alpha + et[j];
    float bv = fin; int bi = j;
#pragma unroll
    for (int off = 16; off; off >>= 1) {
        float ovv = __shfl_down_sync(0xffffffffu, bv, off);
        int oi = __shfl_down_sync(0xffffffffu, bi, off);
        if (ovv > bv || (ovv == bv && oi < bi)) { bv = ovv; bi = oi; }
    }
    if (j == 0) {
        scores_out[b] = bv;
        int tg = bi;
        for (int t = 511; t >= 1; t--) {
            tags_out[(size_t)b * Ssz + t] = (t < len) ? (float)tg : 0.f;
            tg = bp[t][tg];
        }
        tags_out[(size_t)b * Ssz] = (float)tg;
    }
}

// ------------------- launch -------------------
extern "C" void kernel_launch(void* const* d_in, const int* in_sizes, int n_in,
                              void* d_out, int out_size) {
    const int*   x       = (const int*)d_in[0];
    const int*   xlen    = (const int*)d_in[1];
    const float* emb     = (const float*)d_in[2];
    const float* w_ih_l0 = (const float*)d_in[3];
    const float* w_hh_l0 = (const float*)d_in[4];
    const float* b_ih_l0 = (const float*)d_in[5];
    const float* b_hh_l0 = (const float*)d_in[6];
    const float* w_ih_l1 = (const float*)d_in[7];
    const float* w_hh_l1 = (const float*)d_in[8];
    const float* b_ih_l1 = (const float*)d_in[9];
    const float* b_hh_l1 = (const float*)d_in[10];
    const float* dw      = (const float*)d_in[11];
    const float* db      = (const float*)d_in[12];
    const float* trans   = (const float*)d_in[13];
    const float* strn    = (const float*)d_in[14];
    const float* etrn    = (const float*)d_in[15];
    float* out = (float*)d_out;

    float *x0, *gx, *h0, *h1;
    cudaGetSymbolAddress((void**)&x0, g_x0);
    cudaGetSymbolAddress((void**)&gx, g_gx);
    cudaGetSymbolAddress((void**)&h0, g_h0);
    cudaGetSymbolAddress((void**)&h1, g_h1);

    const size_t GXD = (size_t)Bsz * Ssz * NG;
    const int RSMEM = (16 * WPITCH + 32 * HPITCH) * 4;
    cudaFuncSetAttribute(k_recur, cudaFuncAttributeMaxDynamicSharedMemorySize, RSMEM);

    k_embed<<<Bsz * Ssz, 64>>>(x, emb, x0);

    // layer 0: K=256
    k_gemm<<<dim3(8, 128), 256>>>(x0, w_ih_l0,            b_ih_l0,      b_hh_l0,      gx,       256, NG);
    k_gemm<<<dim3(8, 128), 256>>>(x0, w_ih_l0 + NG * 256, b_ih_l0 + NG, b_hh_l0 + NG, gx + GXD, 256, NG);
    k_recur<<<128, 128, RSMEM>>>(gx, w_hh_l0, xlen, h0);

    // layer 1: K=512
    k_gemm<<<dim3(8, 128), 256>>>(h0, w_ih_l1,            b_ih_l1,      b_hh_l1,      gx,       512, NG);
    k_gemm<<<dim3(8, 128), 256>>>(h0, w_ih_l1 + NG * 512, b_ih_l1 + NG, b_hh_l1 + NG, gx + GXD, 512, NG);
    k_recur<<<128, 128, RSMEM>>>(gx, w_hh_l1, xlen, h1);

    k_emis<<<512, 256>>>(h1, dw, db, out);

    float* tags   = out + (size_t)Bsz * Ssz * Lsz;
    float* scores = tags + (size_t)Bsz * Ssz;
    k_viterbi<<<Bsz, 32>>>(out, xlen, trans, strn, etrn, tags, scores);
}

// round 4
// speedup vs baseline: 1.0355x; 1.0355x over previous
#include <cuda_runtime.h>
#include <math.h>

#define Bsz 32
#define Ssz 512
#define Esz 256
#define HDz 256
#define Hsz 512
#define Lsz 32
#define NG  1024   // 4*HD gate rows per direction
#define RPITCH 268 // smem pitch (floats): 16B-aligned rows, 2-phase LDS.128

// ------------------- scratch -------------------
__device__ float g_x0[Bsz * Ssz * Esz];                 // embed out
__device__ float g_gx[2 * Bsz * Ssz * NG];              // gate preacts, both dirs
__device__ float g_h0[Bsz * Ssz * Hsz];                 // layer0 out
__device__ float g_h1[Bsz * Ssz * Hsz];                 // layer1 out
__device__ float g_ring2[2 * 8 * 2 * 4 * 256];          // [dir][bgroup][buf][b_local][unit]

// ------------------- packed f32x2 helpers -------------------
__device__ __forceinline__ void dfma2(unsigned long long& d, unsigned long long a,
                                      unsigned long long b) {
    asm("fma.rn.f32x2 %0, %1, %2, %0;" : "+l"(d) : "l"(a), "l"(b));
}
__device__ __forceinline__ float2 up2(unsigned long long v) {
    float2 f;
    asm("mov.b64 {%0, %1}, %2;" : "=f"(f.x), "=f"(f.y) : "l"(v));
    return f;
}
__device__ __forceinline__ unsigned long long dupf(float b) {
    unsigned long long r;
    asm("mov.b64 %0, {%1, %1};" : "=l"(r) : "f"(b));
    return r;
}

// ------------------- embed -------------------
__global__ void k_embed(const int* __restrict__ x, const float* __restrict__ emb,
                        float* __restrict__ out) {
    int row = blockIdx.x;
    int t = threadIdx.x;               // 64 threads
    int tok = x[row];
    const float4* s = (const float4*)(emb + (size_t)tok * Esz);
    ((float4*)(out + (size_t)row * Esz))[t] = s[t];
}

// ------------------- GEMM: C[M,N] = A[M,K] @ W[N,K]^T + b1 + b2 -------------------
// BM=BN=128, BK=8, 256 threads, 8x8 per thread, FMA2 packed along M (no smem dup)
__global__ __launch_bounds__(256) void k_gemm(const float* __restrict__ A,
                                              const float* __restrict__ W,
                                              const float* __restrict__ b1,
                                              const float* __restrict__ b2,
                                              float* __restrict__ C,
                                              int K, int N) {
    __shared__ __align__(16) float As[8][132];
    __shared__ __align__(16) float Bs[8][132];
    int m0 = blockIdx.y * 128, n0 = blockIdx.x * 128;
    int tid = threadIdx.x;
    int tx = tid & 15, ty = tid >> 4;
    int lr = tid >> 1;
    int lk = (tid & 1) * 4;
    const float* Ap = A + (size_t)(m0 + lr) * K + lk;
    const float* Wp = W + (size_t)(n0 + lr) * K + lk;

    unsigned long long acc[4][8];
#pragma unroll
    for (int i = 0; i < 4; i++)
#pragma unroll
        for (int j = 0; j < 8; j++) acc[i][j] = 0ull;

    float4 av = *(const float4*)(Ap);
    float4 bv = *(const float4*)(Wp);

    for (int k0 = 0; k0 < K; k0 += 8) {
        __syncthreads();
        As[lk + 0][lr] = av.x; As[lk + 1][lr] = av.y;
        As[lk + 2][lr] = av.z; As[lk + 3][lr] = av.w;
        Bs[lk + 0][lr] = bv.x; Bs[lk + 1][lr] = bv.y;
        Bs[lk + 2][lr] = bv.z; Bs[lk + 3][lr] = bv.w;
        __syncthreads();
        float4 av_n = av, bv_n = bv;
        if (k0 + 8 < K) {
            av_n = *(const float4*)(Ap + k0 + 8);
            bv_n = *(const float4*)(Wp + k0 + 8);
        }
#pragma unroll
        for (int kk = 0; kk < 8; kk++) {
            ulonglong2 A0 = *(const ulonglong2*)&As[kk][ty * 4];       // m-pairs 0,1
            ulonglong2 A1 = *(const ulonglong2*)&As[kk][64 + ty * 4];  // m-pairs 2,3
            float4 q0 = *(const float4*)&Bs[kk][tx * 4];
            float4 q1 = *(const float4*)&Bs[kk][64 + tx * 4];
            unsigned long long am[4] = {A0.x, A0.y, A1.x, A1.y};
            unsigned long long bd[8] = {dupf(q0.x), dupf(q0.y), dupf(q0.z), dupf(q0.w),
                                        dupf(q1.x), dupf(q1.y), dupf(q1.z), dupf(q1.w)};
#pragma unroll
            for (int mp = 0; mp < 4; mp++)
#pragma unroll
                for (int j = 0; j < 8; j++) dfma2(acc[mp][j], am[mp], bd[j]);
        }
        av = av_n; bv = bv_n;
    }

#pragma unroll
    for (int mp = 0; mp < 4; mp++) {
        int r = m0 + ((mp < 2) ? ty * 4 + 2 * mp : 64 + ty * 4 + 2 * (mp - 2));
#pragma unroll
        for (int j = 0; j < 8; j++) {
            int c = n0 + ((j < 4) ? 4 * tx + j : 64 + 4 * tx + (j - 4));
            float2 f = up2(acc[mp][j]);
            float bb = b1[c] + b2[c];
            C[(size_t)r * N + c]       = f.x + bb;
            C[(size_t)(r + 1) * N + c] = f.y + bb;
        }
    }
}

__device__ __forceinline__ float sigm(float x) { return 1.f / (1.f + expf(-x)); }

// ------------------- BiLSTM recurrence (batch-partitioned, cluster-synced) -------------------
// grid (8, 16): x = unit-slice (cluster dim), y = dir*8 + bgroup. 256 threads.
// CTA: 32 units (128 gate-cols) x 4 batches. thread: col = t>>1, bpair = t&1.
__global__ __launch_bounds__(256) __cluster_dims__(8, 1, 1)
void k_recur(const float* __restrict__ gx, const float* __restrict__ w_hh,
             const int* __restrict__ xlen, float* __restrict__ hout) {
    extern __shared__ float sm[];
    float* w_s = sm;                       // [128][RPITCH]
    float* h_s = sm + 128 * RPITCH;        // [4][RPITCH]
    int us  = blockIdx.x;
    int dir = blockIdx.y >> 3;
    int bg  = blockIdx.y & 7;
    int U0 = us * 32, B0 = bg * 4;
    int t = threadIdx.x;
    int col = t >> 1, bp = t & 1;
    int b0 = 2 * bp, b1 = 2 * bp + 1;
    int grow = (col & 3) * 256 + U0 + (col >> 2);

    const float* wd  = w_hh + (size_t)dir * NG * HDz;
    const float* gxd = gx + (size_t)dir * ((size_t)Bsz * Ssz * NG);
    float* ring = g_ring2 + (size_t)(dir * 8 + bg) * 2048;   // 2 bufs x 1024

    // load w slice: w_s[c][k] = w_hh[gate*256 + U0 + ul][k]
    for (int idx = t; idx < 128 * 256; idx += 256) {
        int c = idx >> 8, k = idx & 255;
        int gr = (c & 3) * 256 + U0 + (c >> 2);
        w_s[c * RPITCH + k] = wd[(size_t)gr * HDz + k];
    }
    for (int idx = t; idx < 4 * RPITCH; idx += 256) h_s[idx] = 0.f;

    int lenA = xlen[B0 + b0], lenB = xlen[B0 + b1];
    float c0s = 0.f, h0s = 0.f, c1s = 0.f, h1s = 0.f;
    __syncthreads();

    const float* wp  = w_s + col * RPITCH;
    const float* hap = h_s + b0 * RPITCH;
    const float* hbp = h_s + b1 * RPITCH;
    bool g0lane = (t & 6) == 0;
    int U = U0 + (t >> 3);

    for (int step = 0; step < 512; step++) {
        int sA = step, sB = step;
        if (dir) {
            sA = (step < lenA) ? (lenA - 1 - step) : step;
            sB = (step < lenB) ? (lenB - 1 - step) : step;
        }
        float gA = __ldg(gxd + ((size_t)(B0 + b0) * Ssz + sA) * NG + grow);
        float gB = __ldg(gxd + ((size_t)(B0 + b1) * Ssz + sB) * NG + grow);

        unsigned long long ac0a = 0, ac0b = 0, ac1a = 0, ac1b = 0;
#pragma unroll 8
        for (int kq = 0; kq < 64; kq++) {
            ulonglong2 w2 = *(const ulonglong2*)(wp + kq * 4);
            ulonglong2 hA = *(const ulonglong2*)(hap + kq * 4);
            ulonglong2 hB = *(const ulonglong2*)(hbp + kq * 4);
            dfma2(ac0a, w2.x, hA.x); dfma2(ac0b, w2.y, hA.y);
            dfma2(ac1a, w2.x, hB.x); dfma2(ac1b, w2.y, hB.y);
        }
        float2 u;
        u = up2(ac0a); float a0 = u.x + u.y;
        u = up2(ac0b); a0 += u.x + u.y; a0 += gA;
        u = up2(ac1a); float a1 = u.x + u.y;
        u = up2(ac1b); a1 += u.x + u.y; a1 += gB;

        // gather gates f,g,o from cols +1,+2,+3 (lanes +2,+4,+6)
        float fA = __shfl_down_sync(0xffffffffu, a0, 2);
        float gGA = __shfl_down_sync(0xffffffffu, a0, 4);
        float oA = __shfl_down_sync(0xffffffffu, a0, 6);
        float fB = __shfl_down_sync(0xffffffffu, a1, 2);
        float gGB = __shfl_down_sync(0xffffffffu, a1, 4);
        float oB = __shfl_down_sync(0xffffffffu, a1, 6);

        if (g0lane) {
            float iv = sigm(a0), fv = sigm(fA), gv = tanhf(gGA), ov = sigm(oA);
            float cn = fv * c0s + iv * gv;
            float hn = ov * tanhf(cn);
            bool m = step < lenA;
            c0s = m ? cn : c0s; h0s = m ? hn : h0s;
            float out0 = m ? hn : 0.f;

            iv = sigm(a1); fv = sigm(fB); gv = tanhf(gGB); ov = sigm(oB);
            cn = fv * c1s + iv * gv;
            hn = ov * tanhf(cn);
            bool m2 = step < lenB;
            c1s = m2 ? cn : c1s; h1s = m2 ? hn : h1s;
            float out1 = m2 ? hn : 0.f;

            float* rw = ring + (step & 1) * 1024;
            rw[b0 * 256 + U] = h0s;
            rw[b1 * 256 + U] = h1s;

            int posA, posB, oc;
            if (!dir) { posA = step; posB = step; oc = U; }
            else {
                posA = m  ? (lenA - 1 - step) : step;
                posB = m2 ? (lenB - 1 - step) : step;
                oc = 256 + U;
            }
            hout[((size_t)(B0 + b0) * Ssz + posA) * Hsz + oc] = out0;
            hout[((size_t)(B0 + b1) * Ssz + posB) * Hsz + oc] = out1;
        }

        if (step == 511) break;
        asm volatile("barrier.cluster.arrive.aligned;" ::: "memory");
        asm volatile("barrier.cluster.wait.aligned;" ::: "memory");

        // stage ring[step&1] -> h_s (1024 floats, one float4 per thread)
        {
            const float4* rc = (const float4*)(ring + (step & 1) * 1024);
            float4 v = __ldcv(rc + t);
            int b = t >> 6, k4 = (t & 63) * 4;
            *(float4*)(h_s + b * RPITCH + k4) = v;
        }
        __syncthreads();
    }
}

// ------------------- emissions: out[M,32] = h[M,512] @ dw[32,512]^T + db -------------------
__global__ __launch_bounds__(256) void k_emis(const float* __restrict__ h,
                                              const float* __restrict__ dw,
                                              const float* __restrict__ db,
                                              float* __restrict__ out) {
    __shared__ float wT[128 * 33];
    __shared__ float hs[32 * 128];
    int tid = threadIdx.x;
    int w = tid >> 5, j = tid & 31;
    int row0 = blockIdx.x * 32;
    float acc[4] = {0.f, 0.f, 0.f, 0.f};
    for (int kc = 0; kc < 4; kc++) {
        __syncthreads();
        for (int idx = tid; idx < 4096; idx += 256) {
            int jj = idx >> 7, k = idx & 127;
            wT[k * 33 + jj] = dw[(size_t)jj * 512 + kc * 128 + k];
        }
        for (int idx = tid; idx < 4096; idx += 256) {
            int r = idx >> 7, k = idx & 127;
            hs[r * 128 + k] = h[(size_t)(row0 + r) * 512 + kc * 128 + k];
        }
        __syncthreads();
#pragma unroll 4
        for (int k = 0; k < 128; k++) {
            float wv = wT[k * 33 + j];
#pragma unroll
            for (int i = 0; i < 4; i++) acc[i] += hs[(w * 4 + i) * 128 + k] * wv;
        }
    }
    float bias = db[j];
#pragma unroll
    for (int i = 0; i < 4; i++)
        out[(size_t)(row0 + w * 4 + i) * 32 + j] = acc[i] + bias;
}

// ------------------- Viterbi: 32 blocks x 32 threads -------------------
__global__ void k_viterbi(const float* __restrict__ em, const int* __restrict__ xlen,
                          const float* __restrict__ trans, const float* __restrict__ st,
                          const float* __restrict__ et,
                          float* __restrict__ tags_out, float* __restrict__ scores_out) {
    __shared__ unsigned char bp[512][32];
    int b = blockIdx.x, j = threadIdx.x;
    int len = xlen[b];
    float tc[32];
#pragma unroll
    for (int i = 0; i < 32; i++) tc[i] = trans[i * 32 + j];
    const float* e = em + (size_t)b * Ssz * Lsz;
    float alpha = st[j] + e[j];
    for (int t = 1; t < 512; t++) {
        if (t < len) {
            float best = -1e30f; int arg = 0;
#pragma unroll
            for (int i = 0; i < 32; i++) {
                float ai = __shfl_sync(0xffffffffu, alpha, i);
                float cand = ai + tc[i];
                if (cand > best) { best = cand; arg = i; }
            }
            alpha = best + e[(size_t)t * 32 + j];
            bp[t][j] = (unsigned char)arg;
        } else {
            bp[t][j] = (unsigned char)j;
        }
    }
    __syncwarp();
    float fin = alpha + et[j];
    float bv = fin; int bi = j;
#pragma unroll
    for (int off = 16; off; off >>= 1) {
        float ovv = __shfl_down_sync(0xffffffffu, bv, off);
        int oi = __shfl_down_sync(0xffffffffu, bi, off);
        if (ovv > bv || (ovv == bv && oi < bi)) { bv = ovv; bi = oi; }
    }
    if (j == 0) {
        scores_out[b] = bv;
        int tg = bi;
        for (int t = 511; t >= 1; t--) {
            tags_out[(size_t)b * Ssz + t] = (t < len) ? (float)tg : 0.f;
            tg = bp[t][tg];
        }
        tags_out[(size_t)b * Ssz] = (float)tg;
    }
}

// ------------------- launch -------------------
extern "C" void kernel_launch(void* const* d_in, const int* in_sizes, int n_in,
                              void* d_out, int out_size) {
    const int*   x       = (const int*)d_in[0];
    const int*   xlen    = (const int*)d_in[1];
    const float* emb     = (const float*)d_in[2];
    const float* w_ih_l0 = (const float*)d_in[3];
    const float* w_hh_l0 = (const float*)d_in[4];
    const float* b_ih_l0 = (const float*)d_in[5];
    const float* b_hh_l0 = (const float*)d_in[6];
    const float* w_ih_l1 = (const float*)d_in[7];
    const float* w_hh_l1 = (const float*)d_in[8];
    const float* b_ih_l1 = (const float*)d_in[9];
    const float* b_hh_l1 = (const float*)d_in[10];
    const float* dw      = (const float*)d_in[11];
    const float* db      = (const float*)d_in[12];
    const float* trans   = (const float*)d_in[13];
    const float* strn    = (const float*)d_in[14];
    const float* etrn    = (const float*)d_in[15];
    float* out = (float*)d_out;

    float *x0, *gx, *h0, *h1;
    cudaGetSymbolAddress((void**)&x0, g_x0);
    cudaGetSymbolAddress((void**)&gx, g_gx);
    cudaGetSymbolAddress((void**)&h0, g_h0);
    cudaGetSymbolAddress((void**)&h1, g_h1);

    const size_t GXD = (size_t)Bsz * Ssz * NG;
    const int RSMEM = (128 + 4) * RPITCH * 4;
    static int smem_set = 0;
    if (!smem_set) {
        cudaFuncSetAttribute(k_recur, cudaFuncAttributeMaxDynamicSharedMemorySize, RSMEM);
        smem_set = 1;
    }

    k_embed<<<Bsz * Ssz, 64>>>(x, emb, x0);

    // layer 0: K=256
    k_gemm<<<dim3(8, 128), 256>>>(x0, w_ih_l0,            b_ih_l0,      b_hh_l0,      gx,       256, NG);
    k_gemm<<<dim3(8, 128), 256>>>(x0, w_ih_l0 + NG * 256, b_ih_l0 + NG, b_hh_l0 + NG, gx + GXD, 256, NG);
    k_recur<<<dim3(8, 16), 256, RSMEM>>>(gx, w_hh_l0, xlen, h0);

    // layer 1: K=512
    k_gemm<<<dim3(8, 128), 256>>>(h0, w_ih_l1,            b_ih_l1,      b_hh_l1,      gx,       512, NG);
    k_gemm<<<dim3(8, 128), 256>>>(h0, w_ih_l1 + NG * 512, b_ih_l1 + NG, b_hh_l1 + NG, gx + GXD, 512, NG);
    k_recur<<<dim3(8, 16), 256, RSMEM>>>(gx, w_hh_l1, xlen, h1);

    k_emis<<<512, 256>>>(h1, dw, db, out);

    float* tags   = out + (size_t)Bsz * Ssz * Lsz;
    float* scores = tags + (size_t)Bsz * Ssz;
    k_viterbi<<<Bsz, 32>>>(out, xlen, trans, strn, etrn, tags, scores);
}